// round 4
// baseline (speedup 1.0000x reference)
#include <cuda_runtime.h>
#include <cstdint>
#include <math.h>

#define Bq 128
#define Tq 512
#define Cq 100
#define Eq 64
#define Hq 256
#define G7 1792   // 7*H
#define KIN 320   // E+H

typedef unsigned long long ull;

// ---- scratch (device globals; no allocation in kernel_launch) ----
static __device__ float g_r[(size_t)Bq * Tq * Eq];          // rec_input
static __device__ float g_gin[(size_t)Bq * Tq * G7];        // input-side gates (+bias)
static __device__ __align__(16) float g_h[2][Bq][Hq];       // ping-pong h_d [buf][b][j]
static __device__ unsigned g_cnt[8];                        // per-group step counters

__device__ __forceinline__ float sigmf_(float x) { return 1.f / (1.f + expf(-x)); }
__device__ __forceinline__ float softplusf_(float x) {
    return fmaxf(x, 0.f) + log1pf(expf(-fabsf(x)));
}
__device__ __forceinline__ void fma2_(ull& d, ull a, ull b) {
    asm volatile("fma.rn.f32x2 %0, %1, %2, %0;" : "+l"(d) : "l"(a), "l"(b));
}
__device__ __forceinline__ ull dup2_(float x) {
    ull d;
    asm("mov.b64 %0, {%1, %1};" : "=l"(d) : "f"(x));
    return d;
}
__device__ __forceinline__ float lo_(ull v) { return __uint_as_float((unsigned)v); }
__device__ __forceinline__ float hi_(ull v) { return __uint_as_float((unsigned)(v >> 32)); }

// ---------------------------------------------------------------------------
// K1: rec_input
// ---------------------------------------------------------------------------
__global__ __launch_bounds__(128) void k_embed(const float* __restrict__ marks,
                                               const float* __restrict__ Wemb) {
    int bt = blockIdx.x;
    __shared__ float sm[Cq];
    int tid = threadIdx.x;
    if (tid < Cq) sm[tid] = marks[(size_t)bt * Cq + tid];
    __syncthreads();
    if (tid < Eq) {
        float cnt = 0.f, s = 0.f;
        #pragma unroll
        for (int c = 0; c < Cq; c++) {
            float m = sm[c];
            cnt += m;
            s = fmaf(m, Wemb[c * Eq + tid], s);
        }
        g_r[(size_t)bt * Eq + tid] = s / fmaxf(cnt, 1.f);
    }
}

// ---------------------------------------------------------------------------
// K2: g_gin[bt, j] = g_r[bt,:] @ W_cell[j, 0:64]^T + b_cell[j]   (f32x2)
// ---------------------------------------------------------------------------
__global__ __launch_bounds__(256) void k_gin(const float* __restrict__ Wc,
                                             const float* __restrict__ bc) {
    __shared__ float As[64 * 68];
    __shared__ float Bs[64 * 132];
    int tid = threadIdx.x;
    int row0 = blockIdx.x * 64, col0 = blockIdx.y * 128;

    #pragma unroll
    for (int i = 0; i < 16; i++) {
        int idx = i * 256 + tid;
        int row = idx >> 6, k = idx & 63;
        As[k * 68 + row] = g_r[(size_t)(row0 + row) * Eq + k];
    }
    #pragma unroll
    for (int i = 0; i < 32; i++) {
        int idx = i * 256 + tid;
        int col = idx >> 6, k = idx & 63;
        Bs[k * 132 + col] = Wc[(size_t)(col0 + col) * KIN + k];
    }
    __syncthreads();

    int tx = tid & 15, ty = tid >> 4;
    ull acc2[4][4];
    #pragma unroll
    for (int i = 0; i < 4; i++)
        #pragma unroll
        for (int p = 0; p < 4; p++) acc2[i][p] = 0ull;

    #pragma unroll 4
    for (int k = 0; k < 64; k++) {
        float4 a = *(const float4*)&As[k * 68 + ty * 4];
        ulonglong2 b01 = *(const ulonglong2*)&Bs[k * 132 + tx * 8];
        ulonglong2 b23 = *(const ulonglong2*)&Bs[k * 132 + tx * 8 + 4];
        ull ad[4] = {dup2_(a.x), dup2_(a.y), dup2_(a.z), dup2_(a.w)};
        #pragma unroll
        for (int i = 0; i < 4; i++) {
            fma2_(acc2[i][0], ad[i], b01.x);
            fma2_(acc2[i][1], ad[i], b01.y);
            fma2_(acc2[i][2], ad[i], b23.x);
            fma2_(acc2[i][3], ad[i], b23.y);
        }
    }

    float bb[8];
    #pragma unroll
    for (int jx = 0; jx < 8; jx++) bb[jx] = bc[col0 + tx * 8 + jx];

    #pragma unroll
    for (int i = 0; i < 4; i++) {
        size_t base = (size_t)(row0 + ty * 4 + i) * G7 + col0 + tx * 8;
        float4 o0 = {lo_(acc2[i][0]) + bb[0], hi_(acc2[i][0]) + bb[1],
                     lo_(acc2[i][1]) + bb[2], hi_(acc2[i][1]) + bb[3]};
        float4 o1 = {lo_(acc2[i][2]) + bb[4], hi_(acc2[i][2]) + bb[5],
                     lo_(acc2[i][3]) + bb[6], hi_(acc2[i][3]) + bb[7]};
        *(float4*)&g_gin[base]     = o0;
        *(float4*)&g_gin[base + 4] = o1;
    }
}

// ---------------------------------------------------------------------------
// K3: initial state -> out[b,0,:], g_h[0], reset sync counters
// ---------------------------------------------------------------------------
__global__ __launch_bounds__(256) void k_init(const float* __restrict__ init,
                                              float* __restrict__ out) {
    int b = blockIdx.x, k = threadIdx.x;
    if (b == 0 && k < 8) g_cnt[k] = 0;
    float s0 = init[k], s1 = init[Hq + k], s2 = init[2 * Hq + k];
    float s3 = init[3 * Hq + k], s4 = init[4 * Hq + k], s5 = init[5 * Hq + k];
    float hd0 = tanhf(s0), cd0 = tanhf(s1), cb0 = tanhf(s2), c0 = tanhf(s3);
    float d0 = softplusf_(s4), o0 = sigmf_(s5);
    size_t base = (size_t)b * (Tq + 1) * (6 * Hq);
    out[base + 0 * Hq + k] = hd0;
    out[base + 1 * Hq + k] = o0;
    out[base + 2 * Hq + k] = cb0;
    out[base + 3 * Hq + k] = c0;
    out[base + 4 * Hq + k] = d0;
    out[base + 5 * Hq + k] = cd0;
    g_h[0][b][k] = hd0;
}

// ---------------------------------------------------------------------------
// K4: recurrence. grid = 128 = 8 batch-groups (16 b) x 16 j-slices (16 j).
//   512 threads, 16 warps = kw(4 k-split) x jh(4 j-quarter).
//   lane = jq(4 j) x bl(8 batch-pairs). Thread tile: 7 gates x 2 batches x 1 j,
//   64 k, fma.rn.f32x2. Phase 2 on threads 0..255: reduce 4 k-partials,
//   nonlinearities, decay, writes. h via L2 + release/acquire step barrier.
// ---------------------------------------------------------------------------
__global__ void __launch_bounds__(512, 1)
k_recur(const float* __restrict__ Wc, const float* __restrict__ ts,
        const float* __restrict__ init, float* __restrict__ out) {
    extern __shared__ float sh[];
    float* Ws  = sh;            // 28672 floats: [(g*64+kq)*16 + j][k&3]
    float* hs  = sh + 28672;    // 4096 floats:  float4[b*64 + (q4 ^ (b>>1)&7)]
    float* red = sh + 32768;    // 8064 floats:  [(kw*7+g)*16 + j][18 b-pad]

    int tid = threadIdx.x;
    int group = blockIdx.x >> 4;     // 0..7
    int rank  = blockIdx.x & 15;     // 0..15
    int j0 = rank * 16;

    // phase-1 identity
    int w = tid >> 5, lane = tid & 31;
    int kw = w & 3, jh = w >> 2;
    int jq = lane >> 3, bl = lane & 7;
    int j1 = jh * 4 + jq;

    // phase-2 identity (threads 0..255)
    int j2 = tid & 15, b2 = (tid >> 4) & 15;
    int jg2 = j0 + j2;
    int bg2 = group * 16 + b2;
    bool p2 = tid < 256;

    // one-time weight load: LDG coalesced along k
    for (int idx = tid; idx < 7 * 16 * 256; idx += 512) {
        int g = idx >> 12, jw = (idx >> 8) & 15, k = idx & 255;
        int row = g * Hq + j0 + jw;
        Ws[((g * 64 + (k >> 2)) * 16 + jw) * 4 + (k & 3)] =
            Wc[(size_t)row * KIN + Eq + k];
    }

    float c_st = 0.f, cb_st = 0.f;
    if (p2) {
        c_st  = tanhf(init[3 * Hq + jg2]);
        cb_st = tanhf(init[2 * Hq + jg2]);
    }
    __syncthreads();

    float4* hs4 = (float4*)hs;

    for (int t = 0; t < Tq; t++) {
        // ---- stage h (16 b x 256 k) from L2 into swizzled SMEM ----
        const float4* gsrc = (const float4*)&g_h[t & 1][group * 16][0];
        #pragma unroll
        for (int r = 0; r < 2; r++) {
            int i = tid + 512 * r;           // 0..1023
            int b = i >> 6, q4 = i & 63;
            float4 v = __ldcg(gsrc + i);
            hs4[b * 64 + (q4 ^ ((b >> 1) & 7) ^ ((b & 1) << 3))] = v;
        }

        // ---- prefetch input-side gates + timestamps (phase-2 identity) ----
        float ain[7], tc = 0.f, tp = 0.f;
        if (p2) {
            size_t gbase = ((size_t)bg2 * Tq + t) * (size_t)G7 + jg2;
            #pragma unroll
            for (int g = 0; g < 7; g++) ain[g] = __ldcs(&g_gin[gbase + g * Hq]);
            tc = ts[bg2 * Tq + t];
            tp = (t > 0) ? ts[bg2 * Tq + t - 1] : 0.f;
        }
        __syncthreads();

        // ---- phase 1: packed-f32x2 GEMM over k-range [kw*64, kw*64+64) ----
        ull acc[7][2];
        #pragma unroll
        for (int g = 0; g < 7; g++) { acc[g][0] = 0ull; acc[g][1] = 0ull; }

        const ulonglong2* hsu = (const ulonglong2*)hs;
        int b0 = 2 * bl, b1 = 2 * bl + 1;
        #pragma unroll 4
        for (int q = 0; q < 16; q++) {
            int q4 = kw * 16 + q;
            ulonglong2 h0 = hsu[b0 * 64 + (q4 ^ bl)];
            ulonglong2 h1 = hsu[b1 * 64 + (q4 ^ bl ^ 8)];
            #pragma unroll
            for (int g = 0; g < 7; g++) {
                ulonglong2 wv = *(const ulonglong2*)&Ws[((g * 64 + q4) * 16 + j1) * 4];
                fma2_(acc[g][0], wv.x, h0.x);
                fma2_(acc[g][0], wv.y, h0.y);
                fma2_(acc[g][1], wv.x, h1.x);
                fma2_(acc[g][1], wv.y, h1.y);
            }
        }

        // ---- store k-partials ----
        #pragma unroll
        for (int g = 0; g < 7; g++) {
            float2 v;
            v.x = lo_(acc[g][0]) + hi_(acc[g][0]);
            v.y = lo_(acc[g][1]) + hi_(acc[g][1]);
            *(float2*)&red[((kw * 7 + g) * 16 + j1) * 18 + 2 * bl] = v;
        }
        __syncthreads();

        // ---- phase 2: reduce + nonlinearities + decay + writes ----
        if (p2) {
            float gate[7];
            #pragma unroll
            for (int g = 0; g < 7; g++) {
                float s = red[((0 * 7 + g) * 16 + j2) * 18 + b2]
                        + red[((1 * 7 + g) * 16 + j2) * 18 + b2]
                        + red[((2 * 7 + g) * 16 + j2) * 18 + b2]
                        + red[((3 * 7 + g) * 16 + j2) * 18 + b2];
                gate[g] = s + ain[g];
            }

            float gi  = sigmf_(gate[0]);
            float gf  = sigmf_(gate[1]);
            float gz  = tanhf(gate[2]);
            float go  = sigmf_(gate[3]);
            float gib = sigmf_(gate[4]);
            float gfb = sigmf_(gate[5]);
            float gd  = softplusf_(gate[6]);
            float dt  = tc - tp;

            float ct  = gf * c_st + gi * gz;
            float cbt = gfb * cb_st + gib * gz;
            float cdt = cbt + (ct - cbt) * expf(-gd * dt);
            float hdt = go * tanhf(cdt);

            size_t ob = ((size_t)bg2 * (Tq + 1) + t + 1) * (size_t)(6 * Hq) + jg2;
            __stcs(&out[ob + 0 * Hq], hdt);
            __stcs(&out[ob + 1 * Hq], go);
            __stcs(&out[ob + 2 * Hq], cbt);
            __stcs(&out[ob + 3 * Hq], ct);
            __stcs(&out[ob + 4 * Hq], gd);
            __stcs(&out[ob + 5 * Hq], cdt);

            c_st = ct; cb_st = cbt;
            __stcg(&g_h[(t & 1) ^ 1][bg2][jg2], hdt);
        }

        // ---- per-group release/acquire step barrier through L2 ----
        __syncthreads();
        if (tid == 0) {
            asm volatile("red.release.gpu.global.add.u32 [%0], %1;"
                         :: "l"(g_cnt + group), "r"(1u) : "memory");
            unsigned target = 16u * (unsigned)(t + 1), v;
            do {
                asm volatile("ld.acquire.gpu.u32 %0, [%1];"
                             : "=r"(v) : "l"(g_cnt + group) : "memory");
            } while (v < target);
        }
        __syncthreads();
    }
}

// ---------------------------------------------------------------------------
extern "C" void kernel_launch(void* const* d_in, const int* in_sizes, int n_in,
                              void* d_out, int out_size) {
    const float* marks = (const float*)d_in[0];
    const float* ts    = (const float*)d_in[1];
    const float* Wemb  = (const float*)d_in[2];
    const float* Wc    = (const float*)d_in[3];
    const float* bc    = (const float*)d_in[4];
    const float* init  = (const float*)d_in[5];
    float* out = (float*)d_out;

    k_embed<<<Bq * Tq, 128>>>(marks, Wemb);
    k_gin<<<dim3((Bq * Tq) / 64, G7 / 128), 256>>>(Wc, bc);
    k_init<<<Bq, 256>>>(init, out);

    const int SMEM = (28672 + 4096 + 8064) * (int)sizeof(float);   // 163,328 B
    cudaFuncSetAttribute(k_recur, cudaFuncAttributeMaxDynamicSharedMemorySize, SMEM);
    k_recur<<<128, 512, SMEM>>>(Wc, ts, init, out);
}